// round 1
// baseline (speedup 1.0000x reference)
#include <cuda_runtime.h>
#include <cuda_bf16.h>

#define Bb 4
#define Ss 1025
#define Ll 1024
#define Ee 1024
#define Hh 16
#define DH 64
#define BH (Bb*Hh)
#define EPSV 1e-5f
#define OUT_ELEMS ((long)Bb*Ss*Ee)

// Scratch (device globals; no runtime allocation)
__device__ float g_Q[Bb*Ll*Ee];
__device__ float g_K[Bb*Ll*Ee];
__device__ float g_V[Bb*Ll*Ee];
__device__ float g_Cp[Bb*Ll*Ee];
__device__ float g_Cc[Bb*Ee];
__device__ float g_Vals[Bb*Ss*Ee];
__device__ float g_qn[BH*Ll];
__device__ float g_cq[BH*Ll];
__device__ float g_cn[BH];

// ---------------------------------------------------------------------------
// SGEMM: C[m,n] = sum_k A[row(m),k] * W[n,k] + bias[n]
// mode 0: A row m at m*Ee (identity)
// mode 1: A = x, skip cls token: row m -> (b*Ss + 1 + l)*Ee
// mode 2: A = x, cls tokens only: row m -> m*Ss*Ee
// ---------------------------------------------------------------------------
__device__ __forceinline__ long arow(int m, int mode) {
    if (mode == 0) return (long)m * Ee;
    if (mode == 1) { int b = m >> 10; int l = m & 1023; return ((long)(b * Ss + 1 + l)) * Ee; }
    return (long)m * Ss * Ee;
}

__global__ __launch_bounds__(256) void sgemm_kernel(
    const float* __restrict__ A, int M, int mode,
    const float* __restrict__ W, const float* __restrict__ bias,
    float* __restrict__ C)
{
    __shared__ float As[16][132];
    __shared__ float Ws[16][132];
    int tid = threadIdx.x;
    int bm = blockIdx.x * 128, bn = blockIdx.y * 128;
    int tx = tid & 15, ty = tid >> 4;
    float acc[8][8];
    #pragma unroll
    for (int i = 0; i < 8; i++)
        #pragma unroll
        for (int j = 0; j < 8; j++) acc[i][j] = 0.f;

    int lm = tid >> 2;
    int lk = (tid & 3) * 4;

    for (int k0 = 0; k0 < Ee; k0 += 16) {
        #pragma unroll
        for (int r = 0; r < 2; r++) {
            int m = bm + lm + r * 64;
            float4 v = make_float4(0.f, 0.f, 0.f, 0.f);
            if (m < M) v = *(const float4*)(A + arow(m, mode) + k0 + lk);
            As[lk + 0][lm + r*64] = v.x;
            As[lk + 1][lm + r*64] = v.y;
            As[lk + 2][lm + r*64] = v.z;
            As[lk + 3][lm + r*64] = v.w;
            int n = bn + lm + r * 64;
            float4 w = *(const float4*)(W + (long)n * Ee + k0 + lk);
            Ws[lk + 0][lm + r*64] = w.x;
            Ws[lk + 1][lm + r*64] = w.y;
            Ws[lk + 2][lm + r*64] = w.z;
            Ws[lk + 3][lm + r*64] = w.w;
        }
        __syncthreads();
        #pragma unroll
        for (int k = 0; k < 16; k++) {
            float ra[8], rb[8];
            *(float4*)&ra[0] = *(float4*)&As[k][ty*8];
            *(float4*)&ra[4] = *(float4*)&As[k][ty*8 + 4];
            *(float4*)&rb[0] = *(float4*)&Ws[k][tx*8];
            *(float4*)&rb[4] = *(float4*)&Ws[k][tx*8 + 4];
            #pragma unroll
            for (int i = 0; i < 8; i++)
                #pragma unroll
                for (int j = 0; j < 8; j++) acc[i][j] += ra[i] * rb[j];
        }
        __syncthreads();
    }

    #pragma unroll
    for (int i = 0; i < 8; i++) {
        int m = bm + ty*8 + i;
        if (m >= M) continue;
        #pragma unroll
        for (int j = 0; j < 8; j += 4) {
            int n = bn + tx*8 + j;
            float4 o;
            o.x = acc[i][j+0] + bias[n+0];
            o.y = acc[i][j+1] + bias[n+1];
            o.z = acc[i][j+2] + bias[n+2];
            o.w = acc[i][j+3] + bias[n+3];
            *(float4*)(C + (long)m * Ee + n) = o;
        }
    }
}

// ---------------------------------------------------------------------------
// Per-(b,h): cn = max(|c|^2, eps); per token j: qn_j, cq_j = c . q_j
// ---------------------------------------------------------------------------
__global__ __launch_bounds__(256) void norms_kernel() {
    int bh = blockIdx.x;
    int b = bh >> 4, h = bh & 15;
    __shared__ float cs[64];
    int tid = threadIdx.x;
    if (tid < 64) cs[tid] = g_Cc[b*Ee + h*DH + tid];
    __syncthreads();
    if (tid == 0) {
        float cn = 0.f;
        #pragma unroll
        for (int t = 0; t < 64; t++) cn += cs[t] * cs[t];
        g_cn[bh] = fmaxf(cn, EPSV);
    }
    for (int j = tid; j < Ll; j += 256) {
        const float* q = g_Q + ((long)(b*Ll + j)) * Ee + h*DH;
        float s = 0.f, d = 0.f;
        #pragma unroll
        for (int t = 0; t < 64; t++) { float qv = q[t]; s += qv * qv; d += qv * cs[t]; }
        g_qn[bh*Ll + j] = fmaxf(s, EPSV);
        g_cq[bh*Ll + j] = d;
    }
}

// ---------------------------------------------------------------------------
// o2c: cls row.  logits = (c.k_j)/sqrt(Dh*cn); softmax; cls_out = attn @ v
// ---------------------------------------------------------------------------
__global__ __launch_bounds__(256) void o2c_kernel() {
    int bh = blockIdx.x; int b = bh >> 4, h = bh & 15;
    __shared__ float cs[64];
    __shared__ float lo[Ll];
    __shared__ float red[256];
    int tid = threadIdx.x;
    if (tid < 64) cs[tid] = g_Cc[b*Ee + h*DH + tid];
    __syncthreads();
    float cn = g_cn[bh];
    float scale = rsqrtf(64.f * cn);
    for (int j = tid; j < Ll; j += 256) {
        const float* k = g_K + ((long)(b*Ll + j)) * Ee + h*DH;
        float d = 0.f;
        #pragma unroll
        for (int t = 0; t < 64; t++) d += k[t] * cs[t];
        lo[j] = d * scale;
    }
    __syncthreads();
    float m = -1e30f;
    for (int j = tid; j < Ll; j += 256) m = fmaxf(m, lo[j]);
    red[tid] = m; __syncthreads();
    for (int s = 128; s > 0; s >>= 1) { if (tid < s) red[tid] = fmaxf(red[tid], red[tid+s]); __syncthreads(); }
    m = red[0]; __syncthreads();
    float ssum = 0.f;
    for (int j = tid; j < Ll; j += 256) { float e = __expf(lo[j] - m); lo[j] = e; ssum += e; }
    __syncthreads();
    red[tid] = ssum; __syncthreads();
    for (int s = 128; s > 0; s >>= 1) { if (tid < s) red[tid] += red[tid+s]; __syncthreads(); }
    float inv = 1.f / red[0];
    __syncthreads();
    int d = tid & 63, grp = tid >> 6;
    float acc = 0.f;
    for (int j = grp; j < Ll; j += 4)
        acc += lo[j] * g_V[((long)(b*Ll + j)) * Ee + h*DH + d];
    red[tid] = acc * inv;
    __syncthreads();
    if (grp == 0) {
        float r = red[d] + red[64+d] + red[128+d] + red[192+d];
        g_Vals[(long)b * Ss * Ee + h*DH + d] = r;
    }
}

// ---------------------------------------------------------------------------
// Fused attention: one block per (b, h, 32-query tile).
// Smem layout (floats):
//   logits  [0, 32768)        32 x 1024
//   cqr     [32768, 33792)
//   Qs      [33792, 35840)    32 x 64
//   sc1/sc2/m1/is1/m2/is2 at 35840.. (32 each)
//   Ks      [36032, 40192)    64 x 65
//   Vs      [40192, 44544)    64 x 68
//   Cs      [44544, 48896)    64 x 68
//   A1      [48896, 51072)    32 x 68
//   A2      [51072, 53248)    32 x 68
// Total 53248 floats = 212992 B
// ---------------------------------------------------------------------------
#define ATTN_SMEM_FLOATS 53248

__global__ __launch_bounds__(256) void attn_kernel(float* __restrict__ attn_out) {
    extern __shared__ float sm[];
    float* logits = sm;
    float* cqr = sm + 32768;
    float* Qs  = sm + 33792;
    float* sc1 = sm + 35840;
    float* sc2 = sm + 35872;
    float* m1s = sm + 35904;
    float* is1 = sm + 35936;
    float* m2s = sm + 35968;
    float* is2 = sm + 36000;
    float* Ks  = sm + 36032;
    float* Vs  = sm + 40192;
    float* Cs  = sm + 44544;
    float* A1  = sm + 48896;
    float* A2  = sm + 51072;

    int tid = threadIdx.x;
    int bh = blockIdx.y; int b = bh >> 4, h = bh & 15;
    int i0 = blockIdx.x * 32;

    for (int idx = tid; idx < 2048; idx += 256) {
        int i = idx >> 6, d = idx & 63;
        Qs[idx] = g_Q[((long)(b*Ll + i0 + i)) * Ee + h*DH + d];
    }
    for (int j = tid; j < Ll; j += 256) cqr[j] = g_cq[bh*Ll + j];
    float cn = g_cn[bh];
    if (tid < 32) {
        float qn = g_qn[bh*Ll + i0 + tid];
        sc1[tid] = rsqrtf(64.f * qn);
        sc2[tid] = rsqrtf(qn * cn);
    }
    __syncthreads();

    int j = tid & 63, ig = tid >> 6;     // ig in 0..3

    // ---- Phase A: logits = (q_i . k_j) * sc1_i  (entire 32x1024 tile) ----
    for (int jt = 0; jt < 16; jt++) {
        {
            int jr = tid >> 2, dq = (tid & 3) * 16;
            const float* src = g_K + ((long)(b*Ll + jt*64 + jr)) * Ee + h*DH + dq;
            #pragma unroll
            for (int s = 0; s < 16; s++) Ks[jr*65 + dq + s] = src[s];
        }
        __syncthreads();
        float acc[8];
        #pragma unroll
        for (int r = 0; r < 8; r++) acc[r] = 0.f;
        #pragma unroll 4
        for (int d = 0; d < 64; d++) {
            float kv = Ks[j*65 + d];
            #pragma unroll
            for (int r = 0; r < 8; r++) acc[r] += Qs[(ig*8 + r)*64 + d] * kv;
        }
        #pragma unroll
        for (int r = 0; r < 8; r++) {
            int i = ig*8 + r;
            logits[i*1024 + jt*64 + j] = acc[r] * sc1[i];
        }
        __syncthreads();
    }

    // ---- Stats: per row, max/sum for both softmaxes ----
    {
        int w = tid >> 5, lane = tid & 31;
        for (int rr = 0; rr < 4; rr++) {
            int i = w*4 + rr;
            float s2v = sc2[i];
            float m1 = -1e30f, m2 = -1e30f;
            for (int jj = lane; jj < 1024; jj += 32) {
                float l = logits[i*1024 + jj];
                m1 = fmaxf(m1, l);
                m2 = fmaxf(m2, l * cqr[jj] * s2v);
            }
            #pragma unroll
            for (int o = 16; o > 0; o >>= 1) {
                m1 = fmaxf(m1, __shfl_xor_sync(0xffffffff, m1, o));
                m2 = fmaxf(m2, __shfl_xor_sync(0xffffffff, m2, o));
            }
            float s1 = 0.f, s2 = 0.f;
            for (int jj = lane; jj < 1024; jj += 32) {
                float l = logits[i*1024 + jj];
                s1 += __expf(l - m1);
                s2 += __expf(l * cqr[jj] * s2v - m2);
            }
            #pragma unroll
            for (int o = 16; o > 0; o >>= 1) {
                s1 += __shfl_xor_sync(0xffffffff, s1, o);
                s2 += __shfl_xor_sync(0xffffffff, s2, o);
            }
            if (lane == 0) { m1s[i] = m1; is1[i] = 1.f/s1; m2s[i] = m2; is2[i] = 1.f/s2; }
        }
    }
    __syncthreads();

    // ---- Phase B: attn writeout + values accumulation ----
    int i2 = tid >> 3, dc = tid & 7;
    float out[8];
    #pragma unroll
    for (int t = 0; t < 8; t++) out[t] = 0.f;

    for (int jt = 0; jt < 16; jt++) {
        {
            int jr = tid >> 2, dq = (tid & 3) * 16;
            const float* vsrc = g_V  + ((long)(b*Ll + jt*64 + jr)) * Ee + h*DH + dq;
            const float* csrc = g_Cp + ((long)(b*Ll + jt*64 + jr)) * Ee + h*DH + dq;
            #pragma unroll
            for (int s = 0; s < 16; s++) {
                Vs[jr*68 + dq + s] = vsrc[s];
                Cs[jr*68 + dq + s] = csrc[s];
            }
        }
        __syncthreads();
        float cqj = cqr[jt*64 + j];
        #pragma unroll
        for (int r = 0; r < 8; r++) {
            int i = ig*8 + r;
            float l = logits[i*1024 + jt*64 + j];
            float a1 = __expf(l - m1s[i]) * is1[i];
            float a2 = __expf(l * cqj * sc2[i] - m2s[i]) * is2[i];
            A1[i*68 + j] = a1;
            A2[i*68 + j] = a2;
            attn_out[((long)bh*Ll + i0 + i) * Ll + jt*64 + j] = a1;
        }
        __syncthreads();
        #pragma unroll 4
        for (int jj = 0; jj < 64; jj++) {
            float a1 = A1[i2*68 + jj];
            float a2 = A2[i2*68 + jj];
            const float* vrow = &Vs[jj*68 + dc*8];
            const float* crow = &Cs[jj*68 + dc*8];
            #pragma unroll
            for (int t = 0; t < 8; t++) out[t] += a1 * vrow[t] + a2 * crow[t];
        }
        __syncthreads();
    }

    {
        long base = ((long)b * Ss + 1 + i0 + i2) * Ee + h*DH + dc*8;
        #pragma unroll
        for (int t = 0; t < 8; t++) g_Vals[base + t] = out[t];
    }
}

// ---------------------------------------------------------------------------
extern "C" void kernel_launch(void* const* d_in, const int* in_sizes, int n_in,
                              void* d_out, int out_size) {
    const float* x  = (const float*)d_in[0];
    const float* Wq = (const float*)d_in[1];
    const float* bq = (const float*)d_in[2];
    const float* Wk = (const float*)d_in[3];
    const float* bk = (const float*)d_in[4];
    const float* Wv = (const float*)d_in[5];
    const float* bv = (const float*)d_in[6];
    const float* Wo = (const float*)d_in[7];
    const float* bo = (const float*)d_in[8];
    const float* Wc = (const float*)d_in[9];
    const float* bc = (const float*)d_in[10];
    float* out = (float*)d_out;

    float *Qp, *Kp, *Vp, *Cpp, *Ccp, *Valsp;
    cudaGetSymbolAddress((void**)&Qp,   g_Q);
    cudaGetSymbolAddress((void**)&Kp,   g_K);
    cudaGetSymbolAddress((void**)&Vp,   g_V);
    cudaGetSymbolAddress((void**)&Cpp,  g_Cp);
    cudaGetSymbolAddress((void**)&Ccp,  g_Cc);
    cudaGetSymbolAddress((void**)&Valsp, g_Vals);

    cudaFuncSetAttribute(attn_kernel, cudaFuncAttributeMaxDynamicSharedMemorySize,
                         ATTN_SMEM_FLOATS * sizeof(float));

    dim3 gProj(32, 8);
    sgemm_kernel<<<gProj, 256>>>(x, Bb*Ll, 1, Wq, bq, Qp);
    sgemm_kernel<<<gProj, 256>>>(x, Bb*Ll, 1, Wk, bk, Kp);
    sgemm_kernel<<<gProj, 256>>>(x, Bb*Ll, 1, Wv, bv, Vp);
    sgemm_kernel<<<gProj, 256>>>(x, Bb*Ll, 1, Wc, bc, Cpp);
    sgemm_kernel<<<dim3(1, 8), 256>>>(x, Bb, 2, Wq, bq, Ccp);

    norms_kernel<<<BH, 256>>>();
    o2c_kernel<<<BH, 256>>>();

    attn_kernel<<<dim3(32, BH), 256, ATTN_SMEM_FLOATS * sizeof(float)>>>(out + OUT_ELEMS);

    sgemm_kernel<<<dim3(33, 8), 256>>>(Valsp, Bb*Ss, 0, Wo, bo, out);
}

// round 2
// speedup vs baseline: 1.6208x; 1.6208x over previous
#include <cuda_runtime.h>
#include <cuda_bf16.h>

#define Bb 4
#define Ss 1025
#define Ll 1024
#define Ee 1024
#define Hh 16
#define DH 64
#define BH (Bb*Hh)
#define EPSV 1e-5f
#define OUT_ELEMS ((long)Bb*Ss*Ee)

// Scratch (device globals; no runtime allocation)
__device__ float g_Q[Bb*Ll*Ee];
__device__ float g_K[Bb*Ll*Ee];
__device__ float g_V[Bb*Ll*Ee];
__device__ float g_Cp[Bb*Ll*Ee];
__device__ float g_Cc[Bb*Ee];
__device__ float g_Vals[Bb*Ss*Ee];
__device__ float g_qn[BH*Ll];
__device__ float g_cq[BH*Ll];
__device__ float g_cn[BH];

// ---------------------------------------------------------------------------
// Fast exp: exp(x) = 2^(x*log2e), magic rounding + degree-5 poly on [-0.5,0.5]
// rel err ~2e-6. All FMA-pipe (no MUFU).
// ---------------------------------------------------------------------------
__device__ __forceinline__ float fexp(float x) {
    float y = x * 1.4426950408889634f;
    float r = y + 12582912.f;                    // 1.5*2^23 magic
    int   n = __float_as_int(r) - 0x4B400000;    // round-to-nearest int(y)
    float f = y - (r - 12582912.f);              // frac in [-0.5, 0.5]
    float p = 1.3333558146e-3f;
    p = fmaf(p, f, 9.6181298421e-3f);
    p = fmaf(p, f, 5.5504108664e-2f);
    p = fmaf(p, f, 2.4022650696e-1f);
    p = fmaf(p, f, 6.9314718056e-1f);
    p = fmaf(p, f, 1.0f);
    return __int_as_float(__float_as_int(p) + (n << 23));
}

// ---------------------------------------------------------------------------
// SGEMM: C[m,n] = sum_k A[row(m),k] * W[n,k] + bias[n]   (unchanged from R1)
// ---------------------------------------------------------------------------
__device__ __forceinline__ long arow(int m, int mode) {
    if (mode == 0) return (long)m * Ee;
    if (mode == 1) { int b = m >> 10; int l = m & 1023; return ((long)(b * Ss + 1 + l)) * Ee; }
    return (long)m * Ss * Ee;
}

__global__ __launch_bounds__(256) void sgemm_kernel(
    const float* __restrict__ A, int M, int mode,
    const float* __restrict__ W, const float* __restrict__ bias,
    float* __restrict__ C)
{
    __shared__ float As[16][132];
    __shared__ float Ws[16][132];
    int tid = threadIdx.x;
    int bm = blockIdx.x * 128, bn = blockIdx.y * 128;
    int tx = tid & 15, ty = tid >> 4;
    float acc[8][8];
    #pragma unroll
    for (int i = 0; i < 8; i++)
        #pragma unroll
        for (int j = 0; j < 8; j++) acc[i][j] = 0.f;

    int lm = tid >> 2;
    int lk = (tid & 3) * 4;

    for (int k0 = 0; k0 < Ee; k0 += 16) {
        #pragma unroll
        for (int r = 0; r < 2; r++) {
            int m = bm + lm + r * 64;
            float4 v = make_float4(0.f, 0.f, 0.f, 0.f);
            if (m < M) v = *(const float4*)(A + arow(m, mode) + k0 + lk);
            As[lk + 0][lm + r*64] = v.x;
            As[lk + 1][lm + r*64] = v.y;
            As[lk + 2][lm + r*64] = v.z;
            As[lk + 3][lm + r*64] = v.w;
            int n = bn + lm + r * 64;
            float4 w = *(const float4*)(W + (long)n * Ee + k0 + lk);
            Ws[lk + 0][lm + r*64] = w.x;
            Ws[lk + 1][lm + r*64] = w.y;
            Ws[lk + 2][lm + r*64] = w.z;
            Ws[lk + 3][lm + r*64] = w.w;
        }
        __syncthreads();
        #pragma unroll
        for (int k = 0; k < 16; k++) {
            float ra[8], rb[8];
            *(float4*)&ra[0] = *(float4*)&As[k][ty*8];
            *(float4*)&ra[4] = *(float4*)&As[k][ty*8 + 4];
            *(float4*)&rb[0] = *(float4*)&Ws[k][tx*8];
            *(float4*)&rb[4] = *(float4*)&Ws[k][tx*8 + 4];
            #pragma unroll
            for (int i = 0; i < 8; i++)
                #pragma unroll
                for (int j = 0; j < 8; j++) acc[i][j] += ra[i] * rb[j];
        }
        __syncthreads();
    }

    #pragma unroll
    for (int i = 0; i < 8; i++) {
        int m = bm + ty*8 + i;
        if (m >= M) continue;
        #pragma unroll
        for (int j = 0; j < 8; j += 4) {
            int n = bn + tx*8 + j;
            float4 o;
            o.x = acc[i][j+0] + bias[n+0];
            o.y = acc[i][j+1] + bias[n+1];
            o.z = acc[i][j+2] + bias[n+2];
            o.w = acc[i][j+3] + bias[n+3];
            *(float4*)(C + (long)m * Ee + n) = o;
        }
    }
}

// ---------------------------------------------------------------------------
// Per-(b,h): cn; per token j: qn_j, cq_j = c . q_j
// ---------------------------------------------------------------------------
__global__ __launch_bounds__(256) void norms_kernel() {
    int bh = blockIdx.x;
    int b = bh >> 4, h = bh & 15;
    __shared__ float cs[64];
    int tid = threadIdx.x;
    if (tid < 64) cs[tid] = g_Cc[b*Ee + h*DH + tid];
    __syncthreads();
    if (tid == 0) {
        float cn = 0.f;
        #pragma unroll
        for (int t = 0; t < 64; t++) cn += cs[t] * cs[t];
        g_cn[bh] = fmaxf(cn, EPSV);
    }
    for (int j = tid; j < Ll; j += 256) {
        const float* q = g_Q + ((long)(b*Ll + j)) * Ee + h*DH;
        float s = 0.f, d = 0.f;
        #pragma unroll
        for (int t = 0; t < 64; t++) { float qv = q[t]; s += qv * qv; d += qv * cs[t]; }
        g_qn[bh*Ll + j] = fmaxf(s, EPSV);
        g_cq[bh*Ll + j] = d;
    }
}

// ---------------------------------------------------------------------------
// o2c: cls row softmax over K, then attn @ V
// ---------------------------------------------------------------------------
__global__ __launch_bounds__(256) void o2c_kernel() {
    int bh = blockIdx.x; int b = bh >> 4, h = bh & 15;
    __shared__ float cs[64];
    __shared__ float lo[Ll];
    __shared__ float red[256];
    int tid = threadIdx.x;
    if (tid < 64) cs[tid] = g_Cc[b*Ee + h*DH + tid];
    __syncthreads();
    float cn = g_cn[bh];
    float scale = rsqrtf(64.f * cn);
    for (int j = tid; j < Ll; j += 256) {
        const float* k = g_K + ((long)(b*Ll + j)) * Ee + h*DH;
        float d = 0.f;
        #pragma unroll
        for (int t = 0; t < 64; t++) d += k[t] * cs[t];
        lo[j] = d * scale;
    }
    __syncthreads();
    float m = -1e30f;
    for (int j = tid; j < Ll; j += 256) m = fmaxf(m, lo[j]);
    red[tid] = m; __syncthreads();
    for (int s = 128; s > 0; s >>= 1) { if (tid < s) red[tid] = fmaxf(red[tid], red[tid+s]); __syncthreads(); }
    m = red[0]; __syncthreads();
    float ssum = 0.f;
    for (int j = tid; j < Ll; j += 256) { float e = fexp(lo[j] - m); lo[j] = e; ssum += e; }
    __syncthreads();
    red[tid] = ssum; __syncthreads();
    for (int s = 128; s > 0; s >>= 1) { if (tid < s) red[tid] += red[tid+s]; __syncthreads(); }
    float inv = 1.f / red[0];
    __syncthreads();
    int d = tid & 63, grp = tid >> 6;
    float acc = 0.f;
    for (int j = grp; j < Ll; j += 4)
        acc += lo[j] * g_V[((long)(b*Ll + j)) * Ee + h*DH + d];
    red[tid] = acc * inv;
    __syncthreads();
    if (grp == 0) {
        float r = red[d] + red[64+d] + red[128+d] + red[192+d];
        g_Vals[(long)b * Ss * Ee + h*DH + d] = r;
    }
}

// ---------------------------------------------------------------------------
// Fused attention, register-tiled. One block per (b,h, 32-query tile).
// Smem (floats):
//   logits [0,32768)         32 x 1024
//   Qs     [32768,34816)     32 x 64
//   cqr    [34816,35840)
//   sc1/sc2/m1s/is1/m2s/is2  [35840,36032)
//   work   [36032,53440)     17408 floats: Ks (256x65=16640) in phase A;
//          Vs(64x68)+Cs(64x68)+A1(32x65)+A2(32x65) in phase B; Rs(3x2048) at end
// Total 53440 floats = 213760 B
// ---------------------------------------------------------------------------
#define ATTN_SMEM_FLOATS 53440

__global__ __launch_bounds__(256) void attn_kernel(float* __restrict__ attn_out) {
    extern __shared__ float sm[];
    float* logits = sm;
    float* Qs  = sm + 32768;
    float* cqr = sm + 34816;
    float* sc1 = sm + 35840;
    float* sc2 = sm + 35872;
    float* m1s = sm + 35904;
    float* is1 = sm + 35936;
    float* m2s = sm + 35968;
    float* is2 = sm + 36000;
    float* work = sm + 36032;
    float* Ks = work;                 // 256 x 65
    float* Vs = work;                 // 64 x 68
    float* Cs = work + 4352;          // 64 x 68
    float* A1 = work + 8704;          // 32 x 65
    float* A2 = work + 10784;         // 32 x 65
    float* Rs = work;                 // 3 x 2048 (end-of-kernel reduction)

    int tid = threadIdx.x;
    int bh = blockIdx.y; int b = bh >> 4, h = bh & 15;
    int i0 = blockIdx.x * 32;

    // ---- prologue: Q tile, cq row, per-row scales ----
    for (int idx = tid; idx < 2048; idx += 256) {
        int i = idx >> 6, d = idx & 63;
        Qs[i*64 + d] = g_Q[((long)(b*Ll + i0 + i)) * Ee + h*DH + d];
    }
    for (int j = tid; j < Ll; j += 256) cqr[j] = g_cq[bh*Ll + j];
    float cn = g_cn[bh];
    if (tid < 32) {
        float qn = g_qn[bh*Ll + i0 + tid];
        sc1[tid] = rsqrtf(64.f * qn);
        sc2[tid] = rsqrtf(qn * cn);
    }
    __syncthreads();

    int ty = tid >> 5, tx = tid & 31;      // ty: i-group (0..7), tx: j lane

    // ---- Phase A: logits = (q_i . k_j) * sc1_i, full 32x1024 tile ----
    for (int jt = 0; jt < 4; jt++) {
        // load 256 K rows (scalar stores, stride 65 => conflict-light)
        for (int t = tid; t < 4096; t += 256) {
            int j = t >> 4, dq = (t & 15) * 4;
            float4 v = *(const float4*)(g_K + ((long)(b*Ll + jt*256 + j)) * Ee + h*DH + dq);
            Ks[j*65 + dq + 0] = v.x;
            Ks[j*65 + dq + 1] = v.y;
            Ks[j*65 + dq + 2] = v.z;
            Ks[j*65 + dq + 3] = v.w;
        }
        __syncthreads();
        float acc[4][8];
        #pragma unroll
        for (int u = 0; u < 4; u++)
            #pragma unroll
            for (int r = 0; r < 8; r++) acc[u][r] = 0.f;
        #pragma unroll 16
        for (int k = 0; k < 64; k++) {
            float q[4], kv[8];
            #pragma unroll
            for (int u = 0; u < 4; u++) q[u] = Qs[(ty*4 + u)*64 + k];
            #pragma unroll
            for (int r = 0; r < 8; r++) kv[r] = Ks[(tx + 32*r)*65 + k];
            #pragma unroll
            for (int u = 0; u < 4; u++)
                #pragma unroll
                for (int r = 0; r < 8; r++) acc[u][r] = fmaf(q[u], kv[r], acc[u][r]);
        }
        #pragma unroll
        for (int u = 0; u < 4; u++) {
            int i = ty*4 + u;
            float s = sc1[i];
            #pragma unroll
            for (int r = 0; r < 8; r++)
                logits[i*1024 + jt*256 + tx + 32*r] = acc[u][r] * s;
        }
        __syncthreads();
    }

    // ---- Stats: per-row max & sum for both softmaxes (warp per 4 rows) ----
    {
        for (int u = 0; u < 4; u++) {
            int i = ty*4 + u;
            float s2v = sc2[i];
            float m1 = -1e30f, m2r = -1e30f;
            for (int jj = tx; jj < 1024; jj += 32) {
                float l = logits[i*1024 + jj];
                m1 = fmaxf(m1, l);
                m2r = fmaxf(m2r, l * cqr[jj]);
            }
            #pragma unroll
            for (int o = 16; o > 0; o >>= 1) {
                m1 = fmaxf(m1, __shfl_xor_sync(0xffffffff, m1, o));
                m2r = fmaxf(m2r, __shfl_xor_sync(0xffffffff, m2r, o));
            }
            float m2 = m2r * s2v;
            float s1 = 0.f, s2 = 0.f;
            for (int jj = tx; jj < 1024; jj += 32) {
                float l = logits[i*1024 + jj];
                s1 += fexp(l - m1);
                s2 += fexp(fmaf(l * cqr[jj], s2v, -m2));
            }
            #pragma unroll
            for (int o = 16; o > 0; o >>= 1) {
                s1 += __shfl_xor_sync(0xffffffff, s1, o);
                s2 += __shfl_xor_sync(0xffffffff, s2, o);
            }
            if (tx == 0) { m1s[i] = m1; is1[i] = 1.f/s1; m2s[i] = m2; is2[i] = 1.f/s2; }
        }
    }
    __syncthreads();

    // ---- Phase B: attn writeout + (a1 V + a2 Cp) as one k=128 GEMM ----
    int g = tid >> 6, t6 = tid & 63;
    int it = t6 >> 3, dt = t6 & 7;           // i-tile (0..7)*4, d-tile (0..7)*8
    float bacc[4][8];
    #pragma unroll
    for (int u = 0; u < 4; u++)
        #pragma unroll
        for (int w = 0; w < 8; w++) bacc[u][w] = 0.f;

    float* attn_base = attn_out + ((long)bh * Ll + i0) * Ll;

    for (int jt = 0; jt < 16; jt++) {
        // load V and Cp 64x64 tiles
        for (int t = tid; t < 1024; t += 256) {
            int j = t >> 4, dq = (t & 15) * 4;
            long src = ((long)(b*Ll + jt*64 + j)) * Ee + h*DH + dq;
            *(float4*)&Vs[j*68 + dq] = *(const float4*)(g_V + src);
            *(float4*)&Cs[j*68 + dq] = *(const float4*)(g_Cp + src);
        }
        // a1/a2 compute: warp ty handles rows ty*4..ty*4+3, lanes cover 64 j
        #pragma unroll
        for (int u = 0; u < 4; u++) {
            int i = ty*4 + u;
            float s2v = sc2[i], mm1 = m1s[i], ii1 = is1[i], mm2 = m2s[i], ii2 = is2[i];
            #pragma unroll
            for (int j2 = 0; j2 < 2; j2++) {
                int j = tx + j2*32;
                float l = logits[i*1024 + jt*64 + j];
                float a1 = fexp(l - mm1) * ii1;
                float a2 = fexp(fmaf(l * cqr[jt*64 + j], s2v, -mm2)) * ii2;
                A1[i*65 + j] = a1;
                A2[i*65 + j] = a2;
                attn_base[(long)i * Ll + jt*64 + j] = a1;
            }
        }
        __syncthreads();
        // GEMM: out(32x64) += [A1|A2](32x128) @ [V;C](128x64), k split by group g
        {
            const float* Am = (g < 2) ? A1 : A2;
            const float* Sm = (g < 2) ? Vs : Cs;
            int jb = (g & 1) * 32;
            #pragma unroll 8
            for (int kk = 0; kk < 32; kk++) {
                int j = jb + kk;
                float a[4];
                #pragma unroll
                for (int u = 0; u < 4; u++) a[u] = Am[(it*4 + u)*65 + j];
                float4 v0 = *(const float4*)&Sm[j*68 + dt*8];
                float4 v1 = *(const float4*)&Sm[j*68 + dt*8 + 4];
                #pragma unroll
                for (int u = 0; u < 4; u++) {
                    bacc[u][0] = fmaf(a[u], v0.x, bacc[u][0]);
                    bacc[u][1] = fmaf(a[u], v0.y, bacc[u][1]);
                    bacc[u][2] = fmaf(a[u], v0.z, bacc[u][2]);
                    bacc[u][3] = fmaf(a[u], v0.w, bacc[u][3]);
                    bacc[u][4] = fmaf(a[u], v1.x, bacc[u][4]);
                    bacc[u][5] = fmaf(a[u], v1.y, bacc[u][5]);
                    bacc[u][6] = fmaf(a[u], v1.z, bacc[u][6]);
                    bacc[u][7] = fmaf(a[u], v1.w, bacc[u][7]);
                }
            }
        }
        __syncthreads();
    }

    // ---- k-group reduction + writeout ----
    if (g > 0) {
        #pragma unroll
        for (int u = 0; u < 4; u++) {
            int base = (g-1)*2048 + (it*4 + u)*64 + dt*8;
            *(float4*)&Rs[base]     = *(float4*)&bacc[u][0];
            *(float4*)&Rs[base + 4] = *(float4*)&bacc[u][4];
        }
    }
    __syncthreads();
    if (g == 0) {
        #pragma unroll
        for (int u = 0; u < 4; u++) {
            int base = (it*4 + u)*64 + dt*8;
            float o[8];
            #pragma unroll
            for (int w = 0; w < 8; w++)
                o[w] = bacc[u][w] + Rs[base + w] + Rs[2048 + base + w] + Rs[4096 + base + w];
            long dst = ((long)(b*Ss + 1 + i0 + it*4 + u)) * Ee + h*DH + dt*8;
            *(float4*)(g_Vals + dst)     = *(float4*)&o[0];
            *(float4*)(g_Vals + dst + 4) = *(float4*)&o[4];
        }
    }
}

// ---------------------------------------------------------------------------
extern "C" void kernel_launch(void* const* d_in, const int* in_sizes, int n_in,
                              void* d_out, int out_size) {
    const float* x  = (const float*)d_in[0];
    const float* Wq = (const float*)d_in[1];
    const float* bq = (const float*)d_in[2];
    const float* Wk = (const float*)d_in[3];
    const float* bk = (const float*)d_in[4];
    const float* Wv = (const float*)d_in[5];
    const float* bv = (const float*)d_in[6];
    const float* Wo = (const float*)d_in[7];
    const float* bo = (const float*)d_in[8];
    const float* Wc = (const float*)d_in[9];
    const float* bc = (const float*)d_in[10];
    float* out = (float*)d_out;

    float *Qp, *Kp, *Vp, *Cpp, *Ccp, *Valsp;
    cudaGetSymbolAddress((void**)&Qp,   g_Q);
    cudaGetSymbolAddress((void**)&Kp,   g_K);
    cudaGetSymbolAddress((void**)&Vp,   g_V);
    cudaGetSymbolAddress((void**)&Cpp,  g_Cp);
    cudaGetSymbolAddress((void**)&Ccp,  g_Cc);
    cudaGetSymbolAddress((void**)&Valsp, g_Vals);

    cudaFuncSetAttribute(attn_kernel, cudaFuncAttributeMaxDynamicSharedMemorySize,
                         ATTN_SMEM_FLOATS * sizeof(float));

    dim3 gProj(32, 8);
    sgemm_kernel<<<gProj, 256>>>(x, Bb*Ll, 1, Wq, bq, Qp);
    sgemm_kernel<<<gProj, 256>>>(x, Bb*Ll, 1, Wk, bk, Kp);
    sgemm_kernel<<<gProj, 256>>>(x, Bb*Ll, 1, Wv, bv, Vp);
    sgemm_kernel<<<gProj, 256>>>(x, Bb*Ll, 1, Wc, bc, Cpp);
    sgemm_kernel<<<dim3(1, 8), 256>>>(x, Bb, 2, Wq, bq, Ccp);

    norms_kernel<<<BH, 256>>>();
    o2c_kernel<<<BH, 256>>>();

    attn_kernel<<<dim3(32, BH), 256, ATTN_SMEM_FLOATS * sizeof(float)>>>(out + OUT_ELEMS);

    sgemm_kernel<<<dim3(33, 8), 256>>>(Valsp, Bb*Ss, 0, Wo, bo, out);
}